// round 2
// baseline (speedup 1.0000x reference)
#include <cuda_runtime.h>
#include <cstdint>

#define N_BATCH 8
#define K_ANCH  9
#define Hdim    120
#define Wdim    120
#define HW      (Hdim*Wdim)
#define TOT     (HW*K_ANCH)       /* 129600 */
#define PRE     3000
#define POST    300
#define NWORDS  47                /* ceil(3000/64) */
#define MPITCH  48
#define CAND_MAX 8192
#define NBUCKET  4096

// ---------------- scratch (static device globals; no allocation) ------------
__device__ int    g_topk_idx[N_BATCH*PRE];
__device__ float  g_topk_score[N_BATCH*PRE];
__device__ float4 g_boxes[N_BATCH*PRE];
__device__ unsigned long long g_mask[(size_t)N_BATCH*PRE*MPITCH];   // ~9.2MB
__device__ float  g_selscore[N_BATCH*POST];

// monotone float->uint key (descending floats -> descending uints)
__device__ __forceinline__ unsigned int fkey(float x) {
    unsigned int u = __float_as_uint(x);
    return (u & 0x80000000u) ? ~u : (u | 0x80000000u);
}
__device__ __forceinline__ float fkey_inv(unsigned int k) {
    return (k & 0x80000000u) ? __uint_as_float(k ^ 0x80000000u)
                             : __uint_as_float(~k);
}

// ---------------- Stage 1: per-batch exact top-3000 -------------------------
extern "C" __global__ void __launch_bounds__(1024)
topk_kernel(const float* __restrict__ cls) {
    extern __shared__ unsigned long long s_cand[];   // 8192 * 8B = 64KB
    __shared__ unsigned int hist[NBUCKET];           // 16KB
    __shared__ unsigned int psum[1024];              // 4KB
    __shared__ unsigned int s_B;
    __shared__ unsigned int s_cnt;

    const int n   = blockIdx.x;
    const int tid = threadIdx.x;
    const float* sc = cls + (size_t)n * TOT;

    for (int b = tid; b < NBUCKET; b += 1024) hist[b] = 0;
    if (tid == 0) s_cnt = 0;
    __syncthreads();

    for (int i = tid; i < TOT; i += 1024)
        atomicAdd(&hist[fkey(sc[i]) >> 20], 1u);
    __syncthreads();

    psum[tid] = hist[4*tid] + hist[4*tid+1] + hist[4*tid+2] + hist[4*tid+3];
    __syncthreads();

    if (tid == 0) {
        unsigned int acc = 0;
        int S = 0;
        for (int s = 31; s >= 0; --s) {
            unsigned int q = 0;
            for (int t = 0; t < 32; ++t) q += psum[s*32 + t];
            if (acc + q >= PRE) { S = s; break; }
            acc += q;
        }
        int Pb = S*32;
        for (int t = 31; t >= 0; --t) {
            unsigned int q = psum[S*32 + t];
            if (acc + q >= PRE) { Pb = S*32 + t; break; }
            acc += q;
        }
        unsigned int B = (unsigned int)(Pb*4);
        for (int b = 3; b >= 0; --b) {
            unsigned int q = hist[Pb*4 + b];
            if (acc + q >= PRE) { B = (unsigned int)(Pb*4 + b); break; }
            acc += q;
        }
        s_B = B;
    }
    __syncthreads();

    const unsigned int thr = s_B << 20;
    for (int i = tid; i < TOT; i += 1024) {
        unsigned int k = fkey(sc[i]);
        if (k >= thr) {
            unsigned int pos = atomicAdd(&s_cnt, 1u);
            if (pos < CAND_MAX)
                s_cand[pos] = ((unsigned long long)k << 32) |
                              (unsigned int)(~(unsigned int)i);
        }
    }
    __syncthreads();

    const unsigned int cnt = s_cnt;               // guaranteed >= PRE
    const int S_sort = (cnt <= 4096u) ? 4096 : 8192;
    for (int i = (int)cnt + tid; i < S_sort; i += 1024) s_cand[i] = 0ull;
    __syncthreads();

    // bitonic sort, descending on u64 (ties: smaller idx first via ~idx)
    for (int k = 2; k <= S_sort; k <<= 1) {
        for (int j = k >> 1; j > 0; j >>= 1) {
            for (int i = tid; i < S_sort; i += 1024) {
                int ixj = i ^ j;
                if (ixj > i) {
                    unsigned long long a = s_cand[i], b = s_cand[ixj];
                    bool dir = (i & k) != 0;
                    if ((a < b) != dir) { s_cand[i] = b; s_cand[ixj] = a; }
                }
            }
            __syncthreads();
        }
    }

    for (int r = tid; r < PRE; r += 1024) {
        unsigned long long c = s_cand[r];
        unsigned int key = (unsigned int)(c >> 32);
        int idx = (int)(~(unsigned int)(c & 0xFFFFFFFFull));
        g_topk_idx[n*PRE + r]   = idx;
        g_topk_score[n*PRE + r] = fkey_inv(key);
    }
}

// ---------------- Stage 2: gather-compute selected boxes --------------------
extern "C" __global__ void boxes_kernel(const float* __restrict__ deltas) {
    int g = blockIdx.x*blockDim.x + threadIdx.x;
    if (g >= N_BATCH*PRE) return;
    const int n = g / PRE;
    const int o = g_topk_idx[g];

    const int kk = o % K_ANCH;
    const int t0 = o / K_ANCH;
    const int ww = t0 % Wdim;
    const int hh = t0 / Wdim;

    const float ratios_[3] = {0.5f, 1.0f, 2.0f};
    const float scales_[3] = {8.0f, 16.0f, 32.0f};

    float v[4];
#pragma unroll
    for (int jj = 0; jj < 4; ++jj) {
        int f  = ((kk*4 + jj)*Hdim + hh)*Wdim + ww;
        int j  = f & 3;
        int r1 = f >> 2;
        int k  = r1 % K_ANCH;
        int r2 = r1 / K_ANCH;
        int w  = r2 % Wdim;
        int h  = r2 / Wdim;

        float sr  = __fsqrt_rn(ratios_[k/3]);
        float wsz = __fdiv_rn(__fmul_rn(16.0f, scales_[k%3]), sr);
        float hsz = __fmul_rn(__fmul_rn(16.0f, scales_[k%3]), sr);
        float cx  = __fmul_rn(__fadd_rn((float)w, 0.5f), 16.0f);
        float cy  = __fmul_rn(__fadd_rn((float)h, 0.5f), 16.0f);

        float a;
        if      (j == 0) a = __fsub_rn(cx, __fmul_rn(0.5f, wsz));
        else if (j == 1) a = __fsub_rn(cy, __fmul_rn(0.5f, hsz));
        else if (j == 2) a = __fadd_rn(cx, __fmul_rn(0.5f, wsz));
        else             a = __fadd_rn(cy, __fmul_rn(0.5f, hsz));

        float d   = deltas[((size_t)n*36 + (k*4 + j))*HW + h*Wdim + w];
        float val = __fadd_rn(a, d);
        v[jj] = fminf(fmaxf(val, 0.0f), 1919.0f);
    }
    g_boxes[g] = make_float4(v[0], v[1], v[2], v[3]);
}

// ---------------- Stage 3: NMS suppression bitmask (division-free) ----------
// iou = fdiv_rn(inter, denom) > 0.5f, computed EXACTLY without division:
// RN(q) > 0.5 <=> q > 0.5 + 2^-25 <=> 2*inter > denom*(1 + 2^-24), exact in
// double (products have <=49-bit mantissas). denom<=0 handled per IEEE fdiv.
extern "C" __global__ void mask_kernel() {
    const int rb = blockIdx.x, cb = blockIdx.y, n = blockIdx.z;
    if (cb < rb) return;
    __shared__ float4 colbox[64];
    __shared__ float  colarea[64];
    const int tid = threadIdx.x;
    const int cj = cb*64 + tid;
    float4 cbx = (cj < PRE) ? g_boxes[n*PRE + cj] : make_float4(0,0,0,0);
    colbox[tid] = cbx;
    colarea[tid] = __fmul_rn(__fadd_rn(__fsub_rn(cbx.z, cbx.x), 1.0f),
                             __fadd_rn(__fsub_rn(cbx.w, cbx.y), 1.0f));
    __syncthreads();

    const int i = rb*64 + tid;
    if (i >= PRE) return;
    const float4 bi = g_boxes[n*PRE + i];
    const float ai = __fmul_rn(__fadd_rn(__fsub_rn(bi.z, bi.x), 1.0f),
                               __fadd_rn(__fsub_rn(bi.w, bi.y), 1.0f));
    unsigned long long bits = 0ull;
    const int jmax = min(64, PRE - cb*64);
    const double one_p = 1.0 + 0x1p-24;
    for (int c = 0; c < jmax; ++c) {
        int j = cb*64 + c;
        if (j <= i) continue;
        float4 bj = colbox[c];
        float aj = colarea[c];
        float xx1 = fmaxf(bi.x, bj.x), yy1 = fmaxf(bi.y, bj.y);
        float xx2 = fminf(bi.z, bj.z), yy2 = fminf(bi.w, bj.w);
        float iw = fmaxf(__fadd_rn(__fsub_rn(xx2, xx1), 1.0f), 0.0f);
        float ih = fmaxf(__fadd_rn(__fsub_rn(yy2, yy1), 1.0f), 0.0f);
        float inter = __fmul_rn(iw, ih);
        float denom = __fsub_rn(__fadd_rn(ai, aj), inter);
        bool sup;
        if (denom > 0.0f)
            sup = (2.0 * (double)inter > (double)denom * one_p);
        else
            sup = (denom == 0.0f) && (inter > 0.0f);   // +inf > 0.5; NaN false
        if (sup) bits |= (1ull << c);
    }
    g_mask[((size_t)n*PRE + i)*MPITCH + cb] = bits;
}

// ---------------- Stage 4: warp-register sequential scan --------------------
// One warp per batch. rem bitset lives in registers (2 words/lane). Next-bit
// search via ballots (uniform result on all lanes), mask row ANDed straight
// from L2 into registers. Output writes deferred to after the loop.
extern "C" __global__ void __launch_bounds__(32)
scan_kernel(float* __restrict__ out) {
    const int n = blockIdx.x;
    const int lane = threadIdx.x;
    __shared__ int s_kept[POST];

    // word assignment: lane holds word[lane] and word[32+lane] (lane<15)
    unsigned long long rem0 = ~0ull;                       // words 0..31
    unsigned long long rem1 =
        (lane < 14) ? ~0ull :
        (lane == 14 ? ((1ull << 56) - 1ull) : 0ull);       // words 32..46

    const unsigned FULL = 0xffffffffu;
    int nk = 0;
    while (nk < POST) {
        unsigned b0 = __ballot_sync(FULL, rem0 != 0ull);
        unsigned b1 = __ballot_sync(FULL, rem1 != 0ull);
        if ((b0 | b1) == 0u) break;
        int w = b0 ? (__ffs(b0) - 1) : (32 + __ffs(b1) - 1);
        unsigned long long v0 = __shfl_sync(FULL, rem0, w & 31);
        unsigned long long v1 = __shfl_sync(FULL, rem1, w & 31);
        unsigned long long word = (w < 32) ? v0 : v1;
        int b = __ffsll((long long)word) - 1;
        int i = w * 64 + b;

        if (lane == (w & 31)) {                 // consume bit i (lowest set)
            unsigned long long nw = word & (word - 1ull);
            if (w < 32) rem0 = nw; else rem1 = nw;
        }
        if (lane == 0) s_kept[nk] = i;
        ++nk;

        const unsigned long long* row =
            g_mask + ((size_t)n * PRE + i) * MPITCH;
        unsigned long long m0 = row[lane];
        unsigned long long m1 = (lane < 15) ? row[32 + lane] : 0ull;
        rem0 &= ~m0;
        rem1 &= ~m1;
    }
    __syncwarp();

    for (int r = lane; r < POST; r += 32) {
        float sc = 0.0f, x1 = 0.0f, y1 = 0.0f, x2 = 0.0f, y2 = 0.0f;
        if (r < nk) {
            int i = s_kept[r];
            float4 bx = g_boxes[n*PRE + i];
            x1 = bx.x; y1 = bx.y; x2 = bx.z; y2 = bx.w;
            sc = g_topk_score[n*PRE + i];
        }
        float* o = out + (size_t)(n*POST + r)*5;
        o[1] = x1; o[2] = y1; o[3] = x2; o[4] = y2;
        g_selscore[n*POST + r] = sc;
    }
}

// ---------------- Stage 5: score column = batch 7's selected scores ---------
extern "C" __global__ void final_kernel(float* __restrict__ out) {
    int g = blockIdx.x*blockDim.x + threadIdx.x;
    if (g >= N_BATCH*POST) return;
    int r = g % POST;
    out[(size_t)g*5] = g_selscore[7*POST + r];
}

// ---------------- launch -----------------------------------------------------
extern "C" void kernel_launch(void* const* d_in, const int* in_sizes, int n_in,
                              void* d_out, int out_size) {
    const float* cls;
    const float* deltas;
    if (in_sizes[0] == N_BATCH*K_ANCH*HW) {     // 1,036,800
        cls = (const float*)d_in[0]; deltas = (const float*)d_in[1];
    } else {
        cls = (const float*)d_in[1]; deltas = (const float*)d_in[0];
    }
    float* out = (float*)d_out;

    cudaFuncSetAttribute(topk_kernel,
                         cudaFuncAttributeMaxDynamicSharedMemorySize, 65536);

    topk_kernel<<<N_BATCH, 1024, 65536>>>(cls);
    boxes_kernel<<<(N_BATCH*PRE + 255)/256, 256>>>(deltas);
    dim3 mg(NWORDS, NWORDS, N_BATCH);
    mask_kernel<<<mg, 64>>>();
    scan_kernel<<<N_BATCH, 32>>>(out);
    final_kernel<<<(N_BATCH*POST + 255)/256, 256>>>(out);
}

// round 3
// speedup vs baseline: 1.2778x; 1.2778x over previous
#include <cuda_runtime.h>
#include <cstdint>

#define N_BATCH 8
#define K_ANCH  9
#define Hdim    120
#define Wdim    120
#define HW      (Hdim*Wdim)
#define TOT     (HW*K_ANCH)       /* 129600 */
#define PRE     3000
#define POST    300
#define NWORDS  47                /* ceil(3000/64) */
#define MPITCH  48
#define CAND_MAX 8192
#define NBUCKET  4096

// ---------------- scratch (static device globals; no allocation) ------------
__device__ int    g_topk_idx[N_BATCH*PRE];
__device__ float  g_topk_score[N_BATCH*PRE];
__device__ float4 g_boxes[N_BATCH*PRE];
__device__ unsigned long long g_mask[(size_t)N_BATCH*PRE*MPITCH];   // ~9.2MB
__device__ float  g_selscore[N_BATCH*POST];

// monotone float->uint key (descending floats -> descending uints)
__device__ __forceinline__ unsigned int fkey(float x) {
    unsigned int u = __float_as_uint(x);
    return (u & 0x80000000u) ? ~u : (u | 0x80000000u);
}
__device__ __forceinline__ float fkey_inv(unsigned int k) {
    return (k & 0x80000000u) ? __uint_as_float(k ^ 0x80000000u)
                             : __uint_as_float(~k);
}

// ---------------- Stage 1: per-batch exact top-3000 -------------------------
extern "C" __global__ void __launch_bounds__(1024)
topk_kernel(const float* __restrict__ cls) {
    extern __shared__ unsigned long long s_cand[];   // 8192 * 8B = 64KB
    __shared__ unsigned int hist[NBUCKET];           // 16KB
    __shared__ unsigned int psum[1024];              // 4KB
    __shared__ unsigned int s_B;
    __shared__ unsigned int s_cnt;

    const int n   = blockIdx.x;
    const int tid = threadIdx.x;
    const float* sc = cls + (size_t)n * TOT;

    for (int b = tid; b < NBUCKET; b += 1024) hist[b] = 0;
    if (tid == 0) s_cnt = 0;
    __syncthreads();

    for (int i = tid; i < TOT; i += 1024)
        atomicAdd(&hist[fkey(sc[i]) >> 20], 1u);
    __syncthreads();

    psum[tid] = hist[4*tid] + hist[4*tid+1] + hist[4*tid+2] + hist[4*tid+3];
    __syncthreads();

    if (tid == 0) {
        unsigned int acc = 0;
        int S = 0;
        for (int s = 31; s >= 0; --s) {
            unsigned int q = 0;
            for (int t = 0; t < 32; ++t) q += psum[s*32 + t];
            if (acc + q >= PRE) { S = s; break; }
            acc += q;
        }
        int Pb = S*32;
        for (int t = 31; t >= 0; --t) {
            unsigned int q = psum[S*32 + t];
            if (acc + q >= PRE) { Pb = S*32 + t; break; }
            acc += q;
        }
        unsigned int B = (unsigned int)(Pb*4);
        for (int b = 3; b >= 0; --b) {
            unsigned int q = hist[Pb*4 + b];
            if (acc + q >= PRE) { B = (unsigned int)(Pb*4 + b); break; }
            acc += q;
        }
        s_B = B;
    }
    __syncthreads();

    const unsigned int thr = s_B << 20;
    for (int i = tid; i < TOT; i += 1024) {
        unsigned int k = fkey(sc[i]);
        if (k >= thr) {
            unsigned int pos = atomicAdd(&s_cnt, 1u);
            if (pos < CAND_MAX)
                s_cand[pos] = ((unsigned long long)k << 32) |
                              (unsigned int)(~(unsigned int)i);
        }
    }
    __syncthreads();

    const unsigned int cnt = s_cnt;               // guaranteed >= PRE
    const int S_sort = (cnt <= 4096u) ? 4096 : 8192;
    for (int i = (int)cnt + tid; i < S_sort; i += 1024) s_cand[i] = 0ull;
    __syncthreads();

    // bitonic sort, descending on u64 (ties: smaller idx first via ~idx)
    for (int k = 2; k <= S_sort; k <<= 1) {
        for (int j = k >> 1; j > 0; j >>= 1) {
            for (int i = tid; i < S_sort; i += 1024) {
                int ixj = i ^ j;
                if (ixj > i) {
                    unsigned long long a = s_cand[i], b = s_cand[ixj];
                    bool dir = (i & k) != 0;
                    if ((a < b) != dir) { s_cand[i] = b; s_cand[ixj] = a; }
                }
            }
            __syncthreads();
        }
    }

    for (int r = tid; r < PRE; r += 1024) {
        unsigned long long c = s_cand[r];
        unsigned int key = (unsigned int)(c >> 32);
        int idx = (int)(~(unsigned int)(c & 0xFFFFFFFFull));
        g_topk_idx[n*PRE + r]   = idx;
        g_topk_score[n*PRE + r] = fkey_inv(key);
    }
}

// ---------------- Stage 2: gather-compute selected boxes --------------------
extern "C" __global__ void boxes_kernel(const float* __restrict__ deltas) {
    int g = blockIdx.x*blockDim.x + threadIdx.x;
    if (g >= N_BATCH*PRE) return;
    const int n = g / PRE;
    const int o = g_topk_idx[g];

    const int kk = o % K_ANCH;
    const int t0 = o / K_ANCH;
    const int ww = t0 % Wdim;
    const int hh = t0 / Wdim;

    const float ratios_[3] = {0.5f, 1.0f, 2.0f};
    const float scales_[3] = {8.0f, 16.0f, 32.0f};

    float v[4];
#pragma unroll
    for (int jj = 0; jj < 4; ++jj) {
        int f  = ((kk*4 + jj)*Hdim + hh)*Wdim + ww;
        int j  = f & 3;
        int r1 = f >> 2;
        int k  = r1 % K_ANCH;
        int r2 = r1 / K_ANCH;
        int w  = r2 % Wdim;
        int h  = r2 / Wdim;

        float sr  = __fsqrt_rn(ratios_[k/3]);
        float wsz = __fdiv_rn(__fmul_rn(16.0f, scales_[k%3]), sr);
        float hsz = __fmul_rn(__fmul_rn(16.0f, scales_[k%3]), sr);
        float cx  = __fmul_rn(__fadd_rn((float)w, 0.5f), 16.0f);
        float cy  = __fmul_rn(__fadd_rn((float)h, 0.5f), 16.0f);

        float a;
        if      (j == 0) a = __fsub_rn(cx, __fmul_rn(0.5f, wsz));
        else if (j == 1) a = __fsub_rn(cy, __fmul_rn(0.5f, hsz));
        else if (j == 2) a = __fadd_rn(cx, __fmul_rn(0.5f, wsz));
        else             a = __fadd_rn(cy, __fmul_rn(0.5f, hsz));

        float d   = deltas[((size_t)n*36 + (k*4 + j))*HW + h*Wdim + w];
        float val = __fadd_rn(a, d);
        v[jj] = fminf(fmaxf(val, 0.0f), 1919.0f);
    }
    g_boxes[g] = make_float4(v[0], v[1], v[2], v[3]);
}

// ---------------- Stage 3: NMS suppression bitmask (fdiv, R1-proven) --------
extern "C" __global__ void mask_kernel() {
    const int rb = blockIdx.x, cb = blockIdx.y, n = blockIdx.z;
    if (cb < rb) return;
    __shared__ float4 colbox[64];
    __shared__ float  colarea[64];
    const int tid = threadIdx.x;
    const int cj = cb*64 + tid;
    float4 cbx = (cj < PRE) ? g_boxes[n*PRE + cj] : make_float4(0,0,0,0);
    colbox[tid] = cbx;
    colarea[tid] = __fmul_rn(__fadd_rn(__fsub_rn(cbx.z, cbx.x), 1.0f),
                             __fadd_rn(__fsub_rn(cbx.w, cbx.y), 1.0f));
    __syncthreads();

    const int i = rb*64 + tid;
    if (i >= PRE) return;
    const float4 bi = g_boxes[n*PRE + i];
    const float ai = __fmul_rn(__fadd_rn(__fsub_rn(bi.z, bi.x), 1.0f),
                               __fadd_rn(__fsub_rn(bi.w, bi.y), 1.0f));
    unsigned long long bits = 0ull;
    const int jmax = min(64, PRE - cb*64);
    for (int c = 0; c < jmax; ++c) {
        int j = cb*64 + c;
        if (j <= i) continue;
        float4 bj = colbox[c];
        float aj = colarea[c];
        float xx1 = fmaxf(bi.x, bj.x), yy1 = fmaxf(bi.y, bj.y);
        float xx2 = fminf(bi.z, bj.z), yy2 = fminf(bi.w, bj.w);
        float iw = fmaxf(__fadd_rn(__fsub_rn(xx2, xx1), 1.0f), 0.0f);
        float ih = fmaxf(__fadd_rn(__fsub_rn(yy2, yy1), 1.0f), 0.0f);
        float inter = __fmul_rn(iw, ih);
        float denom = __fsub_rn(__fadd_rn(ai, aj), inter);
        float iou   = __fdiv_rn(inter, denom);
        if (iou > 0.5f) bits |= (1ull << c);
    }
    g_mask[((size_t)n*PRE + i)*MPITCH + cb] = bits;
}

// ---------------- Stage 4: warp scan with speculative row prefetch ----------
// One warp per batch. rem bitset in registers (words 0..31 on lanes via rem0,
// words 32..46 on lanes 0..14 via rem1). Each iteration prefetches the mask
// rows of the first 4 pre-suppression candidates so the L2 latency of the
// next row is (usually) off the critical path.
extern "C" __global__ void __launch_bounds__(32)
scan_kernel(float* __restrict__ out) {
    const int n = blockIdx.x;
    const int lane = threadIdx.x;
    __shared__ int s_kept[POST];
    const unsigned FULL = 0xffffffffu;

    unsigned long long rem0 = ~0ull;                       // words 0..31
    unsigned long long rem1 =
        (lane < 14) ? ~0ull :
        (lane == 14 ? ((1ull << 56) - 1ull) : 0ull);       // words 32..46

    const unsigned long long* __restrict__ mbase =
        g_mask + (size_t)n * PRE * MPITCH;

    // first kept box is always index 0 (rem starts all-ones)
    int i = 0;
    if (lane == 0) rem0 &= ~1ull;
    unsigned long long m0 = mbase[lane];
    unsigned long long m1 = (lane < 15) ? mbase[32 + lane] : 0ull;

    int nk = 0;
    while (true) {
        s_kept[nk] = i;                 // all lanes, same value: benign
        ++nk;
        if (nk >= POST) break;

        // --- candidates: first up-to-4 set bits of rem (pre-suppression) ---
        unsigned bb0 = __ballot_sync(FULL, rem0 != 0ull);
        unsigned bb1 = __ballot_sync(FULL, rem1 != 0ull);
        if ((bb0 | bb1) == 0u) break;   // nothing left at all

        int wA, wB;
        if (bb0) {
            wA = __ffs(bb0) - 1;
            unsigned r = bb0 & (bb0 - 1u);
            wB = r ? (__ffs(r) - 1) : (bb1 ? 32 + __ffs(bb1) - 1 : -1);
        } else {
            wA = 32 + __ffs(bb1) - 1;
            unsigned r = bb1 & (bb1 - 1u);
            wB = r ? (32 + __ffs(r) - 1) : -1;
        }
        unsigned long long wordA =
            __shfl_sync(FULL, (wA < 32) ? rem0 : rem1, wA & 31);
        unsigned long long wordB = 0ull;
        if (wB >= 0)
            wordB = __shfl_sync(FULL, (wB < 32) ? rem0 : rem1, wB & 31);

        int cand[4];
        {
            unsigned long long tA = wordA, tB = wordB;
            const int baseA = wA * 64, baseB = wB * 64;
#pragma unroll
            for (int q = 0; q < 4; ++q) {
                if (tA) {
                    cand[q] = baseA + __ffsll((long long)tA) - 1;
                    tA &= tA - 1ull;
                } else if (tB) {
                    cand[q] = baseB + __ffsll((long long)tB) - 1;
                    tB &= tB - 1ull;
                } else cand[q] = -1;
            }
        }

        // --- issue prefetch loads for all 4 candidate rows ---
        unsigned long long pf0[4], pf1[4];
#pragma unroll
        for (int q = 0; q < 4; ++q) {
            int c = (cand[q] >= 0) ? cand[q] : 0;
            const unsigned long long* row = mbase + (size_t)c * MPITCH;
            pf0[q] = row[lane];
            pf1[q] = (lane < 15) ? row[32 + lane] : 0ull;
        }

        // --- apply current kept box's suppression row ---
        rem0 &= ~m0;
        rem1 &= ~m1;

        // --- actual next survivor ---
        bb0 = __ballot_sync(FULL, rem0 != 0ull);
        bb1 = __ballot_sync(FULL, rem1 != 0ull);
        if ((bb0 | bb1) == 0u) break;
        int w = bb0 ? (__ffs(bb0) - 1) : (32 + __ffs(bb1) - 1);
        unsigned long long word =
            __shfl_sync(FULL, (w < 32) ? rem0 : rem1, w & 31);
        int inext = w * 64 + __ffsll((long long)word) - 1;

        // consume bit inext (it's the lowest set bit of the owning word)
        if (lane == (w & 31)) {
            if (w < 32) rem0 &= rem0 - 1ull;
            else        rem1 &= rem1 - 1ull;
        }

        // --- select prefetched row, or fall back to direct load ---
        bool hit = false;
#pragma unroll
        for (int q = 0; q < 4; ++q) {
            if (inext == cand[q]) { m0 = pf0[q]; m1 = pf1[q]; hit = true; }
        }
        if (!hit) {
            const unsigned long long* row = mbase + (size_t)inext * MPITCH;
            m0 = row[lane];
            m1 = (lane < 15) ? row[32 + lane] : 0ull;
        }
        i = inext;
    }
    __syncwarp();

    for (int r = lane; r < POST; r += 32) {
        float sc = 0.0f, x1 = 0.0f, y1 = 0.0f, x2 = 0.0f, y2 = 0.0f;
        if (r < nk) {
            int idx = s_kept[r];
            float4 bx = g_boxes[n*PRE + idx];
            x1 = bx.x; y1 = bx.y; x2 = bx.z; y2 = bx.w;
            sc = g_topk_score[n*PRE + idx];
        }
        float* o = out + (size_t)(n*POST + r)*5;
        o[1] = x1; o[2] = y1; o[3] = x2; o[4] = y2;
        g_selscore[n*POST + r] = sc;
    }
}

// ---------------- Stage 5: score column = batch 7's selected scores ---------
extern "C" __global__ void final_kernel(float* __restrict__ out) {
    int g = blockIdx.x*blockDim.x + threadIdx.x;
    if (g >= N_BATCH*POST) return;
    int r = g % POST;
    out[(size_t)g*5] = g_selscore[7*POST + r];
}

// ---------------- launch -----------------------------------------------------
extern "C" void kernel_launch(void* const* d_in, const int* in_sizes, int n_in,
                              void* d_out, int out_size) {
    const float* cls;
    const float* deltas;
    if (in_sizes[0] == N_BATCH*K_ANCH*HW) {     // 1,036,800
        cls = (const float*)d_in[0]; deltas = (const float*)d_in[1];
    } else {
        cls = (const float*)d_in[1]; deltas = (const float*)d_in[0];
    }
    float* out = (float*)d_out;

    cudaFuncSetAttribute(topk_kernel,
                         cudaFuncAttributeMaxDynamicSharedMemorySize, 65536);

    topk_kernel<<<N_BATCH, 1024, 65536>>>(cls);
    boxes_kernel<<<(N_BATCH*PRE + 255)/256, 256>>>(deltas);
    dim3 mg(NWORDS, NWORDS, N_BATCH);
    mask_kernel<<<mg, 64>>>();
    scan_kernel<<<N_BATCH, 32>>>(out);
    final_kernel<<<(N_BATCH*POST + 255)/256, 256>>>(out);
}